// round 9
// baseline (speedup 1.0000x reference)
#include <cuda_runtime.h>
#include <cuda_bf16.h>
#include <math.h>

#define NN 4096
#define IN_DIM 1433
#define HID 64
#define OUT_DIM 7
#define MAXDEG 160
#define SCAD_A 3.7f
#define LAMW ((float)(1.0/0.9 - 1.0))
#define K_STEPS 10
#define KT 32
#define NTILE ((IN_DIM + KT - 1) / KT)   // 45
#define IBLK 128                          // persistent grid (<=148 SMs, all resident)

// ---------------- device globals ----------------
__device__ float  g_F0[NN * 8];
__device__ float  g_NdA[NN * 8];          // {Fn[0..6], sq} ping
__device__ float  g_NdB[NN * 8];          // pong
__device__ float4 g_meta[NN];             // {rD, D, deg(bits), 0}
__device__ float  g_lam[K_STEPS];
__device__ int    g_cols[NN * MAXDEG];
__device__ unsigned g_bar_cnt;
__device__ unsigned g_bar_epoch;

typedef unsigned long long ull;

__device__ __forceinline__ ull pack_dup(float v) {
    ull r; asm("mov.b64 %0, {%1, %1};" : "=l"(r) : "f"(v)); return r;
}
__device__ __forceinline__ void fma2(ull& d, ull a, ull b) {
    asm("fma.rn.f32x2 %0, %1, %2, %0;" : "+l"(d) : "l"(a), "l"(b));
}
__device__ __forceinline__ void unpack2(ull p, float& lo, float& hi) {
    asm("mov.b64 {%0, %1}, %2;" : "=f"(lo), "=f"(hi) : "l"(p));
}
__device__ __forceinline__ float shx(float v, int m) {
    return __shfl_xor_sync(0xffffffffu, v, m);
}

// ============================================================================
// Kernel 1: adjacency — one row per warp, 512 blocks x 256 threads
// ============================================================================
__global__ __launch_bounds__(256)
void build_adj(const float* __restrict__ A,
               const float* __restrict__ lg0p,
               const float* __restrict__ rawp) {
    int warp = threadIdx.x >> 5, lane = threadIdx.x & 31;
    int r = blockIdx.x * 8 + warp;
    const float4* row4 = (const float4*)(A + (size_t)r * NN);
    int* cols = g_cols + (size_t)r * MAXDEG;
    unsigned below = (1u << lane) - 1u;
    int cnt = 0;

    #pragma unroll 1
    for (int c0 = 0; c0 < NN; c0 += 256) {
        float4 va = row4[(c0 >> 2) + lane];
        float4 vb = row4[(c0 >> 2) + 32 + lane];
        unsigned mk = 0;
        mk |= (va.x != 0.0f) ? 1u   : 0u;
        mk |= (va.y != 0.0f) ? 2u   : 0u;
        mk |= (va.z != 0.0f) ? 4u   : 0u;
        mk |= (va.w != 0.0f) ? 8u   : 0u;
        mk |= (vb.x != 0.0f) ? 16u  : 0u;
        mk |= (vb.y != 0.0f) ? 32u  : 0u;
        mk |= (vb.z != 0.0f) ? 64u  : 0u;
        mk |= (vb.w != 0.0f) ? 128u : 0u;
        int c = __popc(mk);
        int pre = 0, tot = 0;
        #pragma unroll
        for (int t = 0; t < 4; t++) {
            unsigned m = __ballot_sync(0xffffffffu, (c >> t) & 1);
            pre += __popc(m & below) << t;
            tot += __popc(m) << t;
        }
        int base = cnt + pre;
        cnt += tot;
        if (mk) {
            int cA = c0 + lane * 4, cB = c0 + 128 + lane * 4;
            if (mk & 1u)   { if (base < MAXDEG) cols[base] = cA + 0; base++; }
            if (mk & 2u)   { if (base < MAXDEG) cols[base] = cA + 1; base++; }
            if (mk & 4u)   { if (base < MAXDEG) cols[base] = cA + 2; base++; }
            if (mk & 8u)   { if (base < MAXDEG) cols[base] = cA + 3; base++; }
            if (mk & 16u)  { if (base < MAXDEG) cols[base] = cB + 0; base++; }
            if (mk & 32u)  { if (base < MAXDEG) cols[base] = cB + 1; base++; }
            if (mk & 64u)  { if (base < MAXDEG) cols[base] = cB + 2; base++; }
            if (mk & 128u) { if (base < MAXDEG) cols[base] = cB + 3; base++; }
        }
    }
    if (lane == 0) {
        int d = cnt < MAXDEG ? cnt : MAXDEG;
        float D = (float)cnt + 1.0f;    // self loop
        g_meta[r] = make_float4(1.0f / sqrtf(D), D, __int_as_float(d), 0.0f);
    }
    if (blockIdx.x == 0 && threadIdx.x == 0) {
        float g0 = expf(lg0p[0]);
        float rr = 1.0f / (1.0f + expf(-rawp[0]));
        float gk = g0;
        #pragma unroll
        for (int k = 0; k < K_STEPS; k++) { g_lam[k] = gk / SCAD_A; gk *= rr; }
    }
}

// ============================================================================
// Kernel 2: mlp_fused — H = relu(X@w1+b1) in smem; F0 = H@w2+b2; Nd seed
// 128 blocks x 256 threads, 32 rows per block
// ============================================================================
__global__ __launch_bounds__(256, 2)
void mlp_fused(const float* __restrict__ X,
               const float* __restrict__ w1,
               const float* __restrict__ b1,
               const float* __restrict__ w2,
               const float* __restrict__ b2) {
    __shared__ __align__(16) ull   Xd[2][KT][33];
    __shared__ __align__(16) float Wsm[2][KT][HID];
    __shared__ float Hs[32][65];
    __shared__ float F0s[32][8];
    __shared__ float w2s[HID * OUT_DIM];
    __shared__ float b2s[OUT_DIM];
    int tid = threadIdx.x;
    int m0 = blockIdx.x * 32;
    int tx = tid & 15;
    int ty = tid >> 4;
    ull acc[2][2] = {{0ull, 0ull}, {0ull, 0ull}};

    for (int idx = tid; idx < HID * OUT_DIM; idx += 256) w2s[idx] = w2[idx];
    if (tid >= 256 - OUT_DIM) b2s[tid - (256 - OUT_DIM)] = b2[tid - (256 - OUT_DIM)];

    float xr0, xr1, xr2, xr3;
    int xrow = tid >> 3;
    int xk   = (tid & 7) * 4;
    float4 wr[2];
    const float* xrow_p = X + (size_t)(m0 + xrow) * IN_DIM;
    {
        xr0 = xrow_p[xk + 0]; xr1 = xrow_p[xk + 1];
        xr2 = xrow_p[xk + 2]; xr3 = xrow_p[xk + 3];
        #pragma unroll
        for (int j = 0; j < 2; j++) {
            int f4 = tid + j * 256;
            int k = f4 >> 4, n4 = f4 & 15;
            wr[j] = *(const float4*)(w1 + (size_t)k * HID + n4 * 4);
        }
    }

    for (int t = 0; t < NTILE; t++) {
        int buf = t & 1;
        __syncthreads();
        Xd[buf][xk + 0][xrow] = pack_dup(xr0);
        Xd[buf][xk + 1][xrow] = pack_dup(xr1);
        Xd[buf][xk + 2][xrow] = pack_dup(xr2);
        Xd[buf][xk + 3][xrow] = pack_dup(xr3);
        #pragma unroll
        for (int j = 0; j < 2; j++) {
            int f4 = tid + j * 256;
            int k = f4 >> 4, n4 = f4 & 15;
            *(float4*)&Wsm[buf][k][n4 * 4] = wr[j];
        }
        if (t + 1 < NTILE) {
            int kt = (t + 1) * KT;
            if (kt + KT <= IN_DIM) {
                xr0 = xrow_p[kt + xk + 0]; xr1 = xrow_p[kt + xk + 1];
                xr2 = xrow_p[kt + xk + 2]; xr3 = xrow_p[kt + xk + 3];
                #pragma unroll
                for (int j = 0; j < 2; j++) {
                    int f4 = tid + j * 256;
                    int k = kt + (f4 >> 4), n4 = f4 & 15;
                    wr[j] = *(const float4*)(w1 + (size_t)k * HID + n4 * 4);
                }
            } else {
                xr0 = (kt + xk + 0 < IN_DIM) ? xrow_p[kt + xk + 0] : 0.0f;
                xr1 = (kt + xk + 1 < IN_DIM) ? xrow_p[kt + xk + 1] : 0.0f;
                xr2 = (kt + xk + 2 < IN_DIM) ? xrow_p[kt + xk + 2] : 0.0f;
                xr3 = (kt + xk + 3 < IN_DIM) ? xrow_p[kt + xk + 3] : 0.0f;
                #pragma unroll
                for (int j = 0; j < 2; j++) {
                    int f4 = tid + j * 256;
                    int k = kt + (f4 >> 4), n4 = f4 & 15;
                    wr[j] = (k < IN_DIM)
                          ? *(const float4*)(w1 + (size_t)k * HID + n4 * 4)
                          : make_float4(0.f, 0.f, 0.f, 0.f);
                }
            }
        }
        __syncthreads();
        #pragma unroll
        for (int k = 0; k < KT; k++) {
            ull ar0 = Xd[buf][k][ty * 2];
            ull ar1 = Xd[buf][k][ty * 2 + 1];
            ulonglong2 b = *(const ulonglong2*)&Wsm[buf][k][tx * 4];
            fma2(acc[0][0], ar0, b.x);
            fma2(acc[0][1], ar0, b.y);
            fma2(acc[1][0], ar1, b.x);
            fma2(acc[1][1], ar1, b.y);
        }
    }

    float4 bv = *(const float4*)&b1[tx * 4];
    #pragma unroll
    for (int r = 0; r < 2; r++) {
        int rl = ty * 2 + r;
        float o0, o1, o2, o3;
        unpack2(acc[r][0], o0, o1);
        unpack2(acc[r][1], o2, o3);
        Hs[rl][tx * 4 + 0] = fmaxf(o0 + bv.x, 0.0f);
        Hs[rl][tx * 4 + 1] = fmaxf(o1 + bv.y, 0.0f);
        Hs[rl][tx * 4 + 2] = fmaxf(o2 + bv.z, 0.0f);
        Hs[rl][tx * 4 + 3] = fmaxf(o3 + bv.w, 0.0f);
    }
    __syncthreads();

    if (tid < 32 * OUT_DIM) {
        int o = tid >> 5, r = tid & 31;
        float a = b2s[o];
        #pragma unroll 16
        for (int k = 0; k < HID; k++) a = fmaf(Hs[r][k], w2s[k * OUT_DIM + o], a);
        F0s[r][o] = a;
    }
    __syncthreads();

    if (tid < 32) {
        int row = m0 + tid;
        float rd = g_meta[row].x;
        float fn[7], ss = 0.0f;
        #pragma unroll
        for (int o = 0; o < 7; o++) {
            float v = F0s[tid][o];
            g_F0[row * 8 + o] = v;
            fn[o] = v * rd;
            ss = fmaf(fn[o], fn[o], ss);
        }
        g_F0[row * 8 + 7] = 0.0f;
        float4* nd = (float4*)(g_NdA + (size_t)row * 8);
        nd[0] = make_float4(fn[0], fn[1], fn[2], fn[3]);
        nd[1] = make_float4(fn[4], fn[5], fn[6], ss);
    }
}

// ============================================================================
// Kernel 3: persistent iterations — 128 blocks x 256 threads, 8 lanes/row
// All 10 diffusion steps in one launch; acq_rel global barrier between steps.
// cols/meta/F0 stay hot in L1 across steps; Nd ping-pong via st.cg/ld.cg.
// ============================================================================
__device__ __forceinline__ void bar_arrive_wait(unsigned target_epoch) {
    __syncthreads();
    if (threadIdx.x == 0) {
        unsigned old;
        asm volatile("atom.add.acq_rel.gpu.u32 %0, [%1], %2;"
                     : "=r"(old) : "l"(&g_bar_cnt), "r"(1u) : "memory");
        if (old == target_epoch * (unsigned)IBLK - 1u) {
            asm volatile("st.release.gpu.u32 [%0], %1;"
                         :: "l"(&g_bar_epoch), "r"(target_epoch) : "memory");
        } else {
            unsigned e;
            do {
                asm volatile("ld.acquire.gpu.u32 %0, [%1];"
                             : "=r"(e) : "l"(&g_bar_epoch) : "memory");
            } while ((int)(e - target_epoch) < 0);
        }
    }
    __syncthreads();
}

__global__ __launch_bounds__(256)
void iter_persistent(float* __restrict__ out) {
    __shared__ unsigned ep0s;
    int tid = threadIdx.x;
    int g = tid & 7;                         // lane in 8-lane row group
    int i = blockIdx.x * 32 + (tid >> 3);    // row

    if (tid == 0) {
        unsigned e;
        asm volatile("ld.acquire.gpu.u32 %0, [%1];" : "=r"(e)
                     : "l"(&g_bar_epoch) : "memory");
        ep0s = e;
    }

    // loop-invariant row state
    float4 meta = g_meta[i];
    float rdi = meta.x, Di = meta.y;
    int deg = __float_as_int(meta.z);
    float F0g = g_F0[(size_t)i * 8 + g];     // slot 7 = 0
    const int4* c4 = (const int4*)(g_cols + (size_t)i * MAXDEG);
    float lam_t[K_STEPS];
    #pragma unroll
    for (int k = 0; k < K_STEPS; k++) lam_t[k] = g_lam[k];
    __syncthreads();
    unsigned ep0 = ep0s;

    #pragma unroll 1
    for (int k = 0; k < K_STEPS; k++) {
        const float* Ndin = (k & 1) ? g_NdB : g_NdA;
        float*       Ndout = (k & 1) ? g_NdA : g_NdB;
        float lam = lam_t[k];
        float alam = SCAD_A * lam;

        const float4* ndi = (const float4*)(Ndin + (size_t)i * 8);
        float4 f0 = __ldcg(ndi), f1 = __ldcg(ndi + 1);
        float fni[7] = {f0.x, f0.y, f0.z, f0.w, f1.x, f1.y, f1.z};
        float sqi = f1.w;

        float t0 = 0.f, t1 = 0.f, t2 = 0.f, t3 = 0.f,
              t4 = 0.f, t5 = 0.f, t6 = 0.f, t7 = 0.f;   // t7 = s

        for (int base = 0; base < deg; base += 32) {
            int4 cc = c4[(base >> 2) + g];
            int e0 = base + g * 4;
            int jj[4] = {cc.x, cc.y, cc.z, cc.w};
            #pragma unroll
            for (int q = 0; q < 4; q++) {
                if (e0 + q < deg) {
                    int j = jj[q];
                    const float4* nj = (const float4*)(Ndin + (size_t)j * 8);
                    float4 a0 = __ldcg(nj), a1 = __ldcg(nj + 1);
                    float dot = fni[0] * a0.x + fni[1] * a0.y + fni[2] * a0.z
                              + fni[3] * a0.w + fni[4] * a1.x + fni[5] * a1.y
                              + fni[6] * a1.z;
                    float Z = fmaxf(sqi + a1.w - 2.0f * dot, 0.0f);
                    float y = sqrtf(Z);
                    float w;
                    if (y <= lam)        w = 1.0f;
                    else if (y <= alam)  w = __fdividef(alam - y,
                                             (SCAD_A - 1.0f) * fmaxf(y, 1e-12f));
                    else                 w = 0.0f;
                    t7 += w;
                    t0 = fmaf(w, a0.x, t0);
                    t1 = fmaf(w, a0.y, t1);
                    t2 = fmaf(w, a0.z, t2);
                    t3 = fmaf(w, a0.w, t3);
                    t4 = fmaf(w, a1.x, t4);
                    t5 = fmaf(w, a1.y, t5);
                    t6 = fmaf(w, a1.z, t6);
                }
            }
        }

        // transposing tree reduce: lane g ends with sum of component g
        bool h4 = (g & 4) != 0, h2 = (g & 2) != 0, h1 = (g & 1) != 0;
        float r0 = shx(h4 ? t0 : t4, 4);
        float r1 = shx(h4 ? t1 : t5, 4);
        float r2 = shx(h4 ? t2 : t6, 4);
        float r3 = shx(h4 ? t3 : t7, 4);
        float u0 = (h4 ? t4 : t0) + r0;
        float u1 = (h4 ? t5 : t1) + r1;
        float u2 = (h4 ? t6 : t2) + r2;
        float u3 = (h4 ? t7 : t3) + r3;
        r0 = shx(h2 ? u0 : u2, 2);
        r1 = shx(h2 ? u1 : u3, 2);
        float w0 = (h2 ? u2 : u0) + r0;
        float w1 = (h2 ? u3 : u1) + r1;
        r0 = shx(h1 ? w0 : w1, 1);
        float tot = (h1 ? w1 : w0) + r0;

        float sT = __shfl_sync(0xffffffffu, tot, 7, 8);   // comp 7 = s
        float Q = sT / Di + LAMW;
        float invQ = 1.0f / Q;
        float f = (rdi * tot + LAMW * F0g) * invQ;

        if (k == K_STEPS - 1) {
            if (g < 7) out[(size_t)i * OUT_DIM + g] = f;
        } else {
            float fn = f * rdi;
            float c = (g < 7) ? fn * fn : 0.0f;
            c += shx(c, 1);
            c += shx(c, 2);
            c += shx(c, 4);
            __stcg(&Ndout[(size_t)i * 8 + g], (g < 7) ? fn : c);
            bar_arrive_wait(ep0 + 1 + (unsigned)k);
        }
    }
}

// ---------------- launch ----------------
extern "C" void kernel_launch(void* const* d_in, const int* in_sizes, int n_in,
                              void* d_out, int out_size) {
    const float *A = nullptr, *X = nullptr, *w1 = nullptr, *b1 = nullptr,
                *w2 = nullptr, *b2 = nullptr, *lg0 = nullptr, *raw = nullptr;
    for (int t = 0; t < n_in; t++) {
        int sz = in_sizes[t];
        const float* p = (const float*)d_in[t];
        if      (sz == NN * NN)        A  = p;
        else if (sz == NN * IN_DIM)    X  = p;
        else if (sz == IN_DIM * HID)   w1 = p;
        else if (sz == HID)            b1 = p;
        else if (sz == HID * OUT_DIM)  w2 = p;
        else if (sz == OUT_DIM)        b2 = p;
        else if (sz == 1) { if (!lg0) lg0 = p; else raw = p; }
    }
    float* out = (float*)d_out;

    build_adj<<<512, 256>>>(A, lg0, raw);
    mlp_fused<<<128, 256>>>(X, w1, b1, w2, b2);
    iter_persistent<<<IBLK, 256>>>(out);
}

// round 10
// speedup vs baseline: 1.2329x; 1.2329x over previous
#include <cuda_runtime.h>
#include <cuda_bf16.h>
#include <math.h>

#define NN 4096
#define IN_DIM 1433
#define HID 64
#define OUT_DIM 7
#define MAXDEG 160
#define SCAD_A 3.7f
#define LAMW ((float)(1.0/0.9 - 1.0))
#define K_STEPS 10
#define KT 32
#define NTILE ((IN_DIM + KT - 1) / KT)   // 45

// ---------------- device globals ----------------
__device__ float  g_F0[NN * 8];
__device__ float  g_NdA[NN * 8];          // {Fn[0..6], sq} ping
__device__ float  g_NdB[NN * 8];          // pong
__device__ float4 g_meta[NN];             // {rD, D, deg(bits), 0}
__device__ float  g_lam[K_STEPS];
__device__ int    g_cols[NN * MAXDEG];

typedef unsigned long long ull;

__device__ __forceinline__ ull pack_dup(float v) {
    ull r; asm("mov.b64 %0, {%1, %1};" : "=l"(r) : "f"(v)); return r;
}
__device__ __forceinline__ void fma2(ull& d, ull a, ull b) {
    asm("fma.rn.f32x2 %0, %1, %2, %0;" : "+l"(d) : "l"(a), "l"(b));
}
__device__ __forceinline__ void unpack2(ull p, float& lo, float& hi) {
    asm("mov.b64 {%0, %1}, %2;" : "=f"(lo), "=f"(hi) : "l"(p));
}
__device__ __forceinline__ float shx(float v, int m) {
    return __shfl_xor_sync(0xffffffffu, v, m);
}

// ============================================================================
// Kernel 1: adjacency — one row per warp, 512 blocks x 256 threads
// ============================================================================
__global__ __launch_bounds__(256)
void build_adj(const float* __restrict__ A,
               const float* __restrict__ lg0p,
               const float* __restrict__ rawp) {
    int warp = threadIdx.x >> 5, lane = threadIdx.x & 31;
    int r = blockIdx.x * 8 + warp;
    const float4* row4 = (const float4*)(A + (size_t)r * NN);
    int* cols = g_cols + (size_t)r * MAXDEG;
    unsigned below = (1u << lane) - 1u;
    int cnt = 0;

    #pragma unroll 2
    for (int c0 = 0; c0 < NN; c0 += 256) {
        float4 va = row4[(c0 >> 2) + lane];
        float4 vb = row4[(c0 >> 2) + 32 + lane];
        unsigned mk = 0;
        mk |= (va.x != 0.0f) ? 1u   : 0u;
        mk |= (va.y != 0.0f) ? 2u   : 0u;
        mk |= (va.z != 0.0f) ? 4u   : 0u;
        mk |= (va.w != 0.0f) ? 8u   : 0u;
        mk |= (vb.x != 0.0f) ? 16u  : 0u;
        mk |= (vb.y != 0.0f) ? 32u  : 0u;
        mk |= (vb.z != 0.0f) ? 64u  : 0u;
        mk |= (vb.w != 0.0f) ? 128u : 0u;
        int c = __popc(mk);
        int pre = 0, tot = 0;
        #pragma unroll
        for (int t = 0; t < 4; t++) {
            unsigned m = __ballot_sync(0xffffffffu, (c >> t) & 1);
            pre += __popc(m & below) << t;
            tot += __popc(m) << t;
        }
        int base = cnt + pre;
        cnt += tot;
        if (mk) {
            int cA = c0 + lane * 4, cB = c0 + 128 + lane * 4;
            if (mk & 1u)   { if (base < MAXDEG) cols[base] = cA + 0; base++; }
            if (mk & 2u)   { if (base < MAXDEG) cols[base] = cA + 1; base++; }
            if (mk & 4u)   { if (base < MAXDEG) cols[base] = cA + 2; base++; }
            if (mk & 8u)   { if (base < MAXDEG) cols[base] = cA + 3; base++; }
            if (mk & 16u)  { if (base < MAXDEG) cols[base] = cB + 0; base++; }
            if (mk & 32u)  { if (base < MAXDEG) cols[base] = cB + 1; base++; }
            if (mk & 64u)  { if (base < MAXDEG) cols[base] = cB + 2; base++; }
            if (mk & 128u) { if (base < MAXDEG) cols[base] = cB + 3; base++; }
        }
    }
    if (lane == 0) {
        int d = cnt < MAXDEG ? cnt : MAXDEG;
        float D = (float)cnt + 1.0f;    // self loop
        g_meta[r] = make_float4(1.0f / sqrtf(D), D, __int_as_float(d), 0.0f);
    }
    if (blockIdx.x == 0 && threadIdx.x == 0) {
        float g0 = expf(lg0p[0]);
        float rr = 1.0f / (1.0f + expf(-rawp[0]));
        float gk = g0;
        #pragma unroll
        for (int k = 0; k < K_STEPS; k++) { g_lam[k] = gk / SCAD_A; gk *= rr; }
    }
}

// ============================================================================
// Kernel 2: mlp_fused — H = relu(X@w1+b1) in smem; F0 = H@w2+b2; Nd seed
// 128 blocks x 256 threads, 32 rows per block
// ============================================================================
__global__ __launch_bounds__(256, 2)
void mlp_fused(const float* __restrict__ X,
               const float* __restrict__ w1,
               const float* __restrict__ b1,
               const float* __restrict__ w2,
               const float* __restrict__ b2) {
    __shared__ __align__(16) ull   Xd[2][KT][33];
    __shared__ __align__(16) float Wsm[2][KT][HID];
    __shared__ float Hs[32][65];
    __shared__ float F0s[32][8];
    __shared__ float w2s[HID * OUT_DIM];
    __shared__ float b2s[OUT_DIM];
    int tid = threadIdx.x;
    int m0 = blockIdx.x * 32;
    int tx = tid & 15;
    int ty = tid >> 4;
    ull acc[2][2] = {{0ull, 0ull}, {0ull, 0ull}};

    for (int idx = tid; idx < HID * OUT_DIM; idx += 256) w2s[idx] = w2[idx];
    if (tid >= 256 - OUT_DIM) b2s[tid - (256 - OUT_DIM)] = b2[tid - (256 - OUT_DIM)];

    float xr0, xr1, xr2, xr3;
    int xrow = tid >> 3;
    int xk   = (tid & 7) * 4;
    float4 wr[2];
    const float* xrow_p = X + (size_t)(m0 + xrow) * IN_DIM;
    {
        xr0 = xrow_p[xk + 0]; xr1 = xrow_p[xk + 1];
        xr2 = xrow_p[xk + 2]; xr3 = xrow_p[xk + 3];
        #pragma unroll
        for (int j = 0; j < 2; j++) {
            int f4 = tid + j * 256;
            int k = f4 >> 4, n4 = f4 & 15;
            wr[j] = *(const float4*)(w1 + (size_t)k * HID + n4 * 4);
        }
    }

    for (int t = 0; t < NTILE; t++) {
        int buf = t & 1;
        __syncthreads();
        Xd[buf][xk + 0][xrow] = pack_dup(xr0);
        Xd[buf][xk + 1][xrow] = pack_dup(xr1);
        Xd[buf][xk + 2][xrow] = pack_dup(xr2);
        Xd[buf][xk + 3][xrow] = pack_dup(xr3);
        #pragma unroll
        for (int j = 0; j < 2; j++) {
            int f4 = tid + j * 256;
            int k = f4 >> 4, n4 = f4 & 15;
            *(float4*)&Wsm[buf][k][n4 * 4] = wr[j];
        }
        if (t + 1 < NTILE) {
            int kt = (t + 1) * KT;
            if (kt + KT <= IN_DIM) {
                xr0 = xrow_p[kt + xk + 0]; xr1 = xrow_p[kt + xk + 1];
                xr2 = xrow_p[kt + xk + 2]; xr3 = xrow_p[kt + xk + 3];
                #pragma unroll
                for (int j = 0; j < 2; j++) {
                    int f4 = tid + j * 256;
                    int k = kt + (f4 >> 4), n4 = f4 & 15;
                    wr[j] = *(const float4*)(w1 + (size_t)k * HID + n4 * 4);
                }
            } else {
                xr0 = (kt + xk + 0 < IN_DIM) ? xrow_p[kt + xk + 0] : 0.0f;
                xr1 = (kt + xk + 1 < IN_DIM) ? xrow_p[kt + xk + 1] : 0.0f;
                xr2 = (kt + xk + 2 < IN_DIM) ? xrow_p[kt + xk + 2] : 0.0f;
                xr3 = (kt + xk + 3 < IN_DIM) ? xrow_p[kt + xk + 3] : 0.0f;
                #pragma unroll
                for (int j = 0; j < 2; j++) {
                    int f4 = tid + j * 256;
                    int k = kt + (f4 >> 4), n4 = f4 & 15;
                    wr[j] = (k < IN_DIM)
                          ? *(const float4*)(w1 + (size_t)k * HID + n4 * 4)
                          : make_float4(0.f, 0.f, 0.f, 0.f);
                }
            }
        }
        __syncthreads();
        #pragma unroll
        for (int k = 0; k < KT; k++) {
            ull ar0 = Xd[buf][k][ty * 2];
            ull ar1 = Xd[buf][k][ty * 2 + 1];
            ulonglong2 b = *(const ulonglong2*)&Wsm[buf][k][tx * 4];
            fma2(acc[0][0], ar0, b.x);
            fma2(acc[0][1], ar0, b.y);
            fma2(acc[1][0], ar1, b.x);
            fma2(acc[1][1], ar1, b.y);
        }
    }

    float4 bv = *(const float4*)&b1[tx * 4];
    #pragma unroll
    for (int r = 0; r < 2; r++) {
        int rl = ty * 2 + r;
        float o0, o1, o2, o3;
        unpack2(acc[r][0], o0, o1);
        unpack2(acc[r][1], o2, o3);
        Hs[rl][tx * 4 + 0] = fmaxf(o0 + bv.x, 0.0f);
        Hs[rl][tx * 4 + 1] = fmaxf(o1 + bv.y, 0.0f);
        Hs[rl][tx * 4 + 2] = fmaxf(o2 + bv.z, 0.0f);
        Hs[rl][tx * 4 + 3] = fmaxf(o3 + bv.w, 0.0f);
    }
    __syncthreads();

    if (tid < 32 * OUT_DIM) {
        int o = tid >> 5, r = tid & 31;
        float a = b2s[o];
        #pragma unroll 16
        for (int k = 0; k < HID; k++) a = fmaf(Hs[r][k], w2s[k * OUT_DIM + o], a);
        F0s[r][o] = a;
    }
    __syncthreads();

    if (tid < 32) {
        int row = m0 + tid;
        float rd = g_meta[row].x;
        float fn[7], ss = 0.0f;
        #pragma unroll
        for (int o = 0; o < 7; o++) {
            float v = F0s[tid][o];
            g_F0[row * 8 + o] = v;
            fn[o] = v * rd;
            ss = fmaf(fn[o], fn[o], ss);
        }
        g_F0[row * 8 + 7] = 0.0f;
        float4* nd = (float4*)(g_NdA + (size_t)row * 8);
        nd[0] = make_float4(fn[0], fn[1], fn[2], fn[3]);
        nd[1] = make_float4(fn[4], fn[5], fn[6], ss);
    }
}

// ============================================================================
// Kernel 3: sparse row update — warp per row, one edge per lane
// 512 blocks x 256 threads; 9-shfl transposing reduce
// ============================================================================
__global__ __launch_bounds__(256)
void row_kernel(int kstep, int last,
                const float* __restrict__ Ndin,
                float* __restrict__ Ndout,
                float* __restrict__ out) {
    int i = (blockIdx.x * 256 + threadIdx.x) >> 5;   // row
    int lane = threadIdx.x & 31;
    int g = lane & 7;

    float lam = g_lam[kstep];
    float alam = SCAD_A * lam;
    float4 meta = g_meta[i];
    float rdi = meta.x, Di = meta.y;
    int deg = __float_as_int(meta.z);
    float F0g = __ldg(&g_F0[(size_t)i * 8 + g]);     // slot 7 = 0
    const float4* ndi = (const float4*)(Ndin + (size_t)i * 8);
    float4 f0 = __ldg(ndi), f1 = __ldg(ndi + 1);
    float fni[7] = {f0.x, f0.y, f0.z, f0.w, f1.x, f1.y, f1.z};
    float sqi = f1.w;
    const int* cols = g_cols + (size_t)i * MAXDEG;

    float t0 = 0.f, t1 = 0.f, t2 = 0.f, t3 = 0.f,
          t4 = 0.f, t5 = 0.f, t6 = 0.f, t7 = 0.f;    // t7 = s

    for (int e = lane; e < deg; e += 32) {
        int j = cols[e];
        const float4* nj = (const float4*)(Ndin + (size_t)j * 8);
        float4 a0 = __ldg(nj), a1 = __ldg(nj + 1);
        float dot = fni[0] * a0.x + fni[1] * a0.y + fni[2] * a0.z
                  + fni[3] * a0.w + fni[4] * a1.x + fni[5] * a1.y
                  + fni[6] * a1.z;
        float Z = fmaxf(sqi + a1.w - 2.0f * dot, 0.0f);
        float y = sqrtf(Z);
        float w;
        if (y <= lam)        w = 1.0f;
        else if (y <= alam)  w = __fdividef(alam - y,
                                            (SCAD_A - 1.0f) * fmaxf(y, 1e-12f));
        else                 w = 0.0f;
        t7 += w;
        t0 = fmaf(w, a0.x, t0);
        t1 = fmaf(w, a0.y, t1);
        t2 = fmaf(w, a0.z, t2);
        t3 = fmaf(w, a0.w, t3);
        t4 = fmaf(w, a1.x, t4);
        t5 = fmaf(w, a1.y, t5);
        t6 = fmaf(w, a1.z, t6);
    }

    // transposing tree reduce within each 8-lane group (7 shfls):
    // afterwards lane (8a+g) has sum of comp g over its 8-lane group
    bool h4 = (g & 4) != 0, h2 = (g & 2) != 0, h1 = (g & 1) != 0;
    float r0 = shx(h4 ? t0 : t4, 4);
    float r1 = shx(h4 ? t1 : t5, 4);
    float r2 = shx(h4 ? t2 : t6, 4);
    float r3 = shx(h4 ? t3 : t7, 4);
    float u0 = (h4 ? t4 : t0) + r0;
    float u1 = (h4 ? t5 : t1) + r1;
    float u2 = (h4 ? t6 : t2) + r2;
    float u3 = (h4 ? t7 : t3) + r3;
    r0 = shx(h2 ? u0 : u2, 2);
    r1 = shx(h2 ? u1 : u3, 2);
    float w0 = (h2 ? u2 : u0) + r0;
    float w1 = (h2 ? u3 : u1) + r1;
    r0 = shx(h1 ? w0 : w1, 1);
    float tot = (h1 ? w1 : w0) + r0;
    // cross-group adds (2 shfls): all 4 groups end replicated with full sums
    tot += shx(tot, 8);
    tot += shx(tot, 16);

    float sT = __shfl_sync(0xffffffffu, tot, 7, 8);   // comp 7 = s
    float Q = sT / Di + LAMW;
    float invQ = 1.0f / Q;
    float f = (rdi * tot + LAMW * F0g) * invQ;

    float fn = f * rdi;
    float c = (g < 7) ? fn * fn : 0.0f;
    c += shx(c, 1);
    c += shx(c, 2);
    c += shx(c, 4);

    if (lane < 8) {                      // group 0 writes
        if (last) {
            if (g < 7) out[(size_t)i * OUT_DIM + g] = f;
        } else {
            Ndout[(size_t)i * 8 + g] = (g < 7) ? fn : c;
        }
    }
}

// ---------------- launch ----------------
extern "C" void kernel_launch(void* const* d_in, const int* in_sizes, int n_in,
                              void* d_out, int out_size) {
    const float *A = nullptr, *X = nullptr, *w1 = nullptr, *b1 = nullptr,
                *w2 = nullptr, *b2 = nullptr, *lg0 = nullptr, *raw = nullptr;
    for (int t = 0; t < n_in; t++) {
        int sz = in_sizes[t];
        const float* p = (const float*)d_in[t];
        if      (sz == NN * NN)        A  = p;
        else if (sz == NN * IN_DIM)    X  = p;
        else if (sz == IN_DIM * HID)   w1 = p;
        else if (sz == HID)            b1 = p;
        else if (sz == HID * OUT_DIM)  w2 = p;
        else if (sz == OUT_DIM)        b2 = p;
        else if (sz == 1) { if (!lg0) lg0 = p; else raw = p; }
    }
    float* out = (float*)d_out;

    build_adj<<<512, 256>>>(A, lg0, raw);
    mlp_fused<<<128, 256>>>(X, w1, b1, w2, b2);

    float *NdA, *NdB;
    cudaGetSymbolAddress((void**)&NdA, g_NdA);
    cudaGetSymbolAddress((void**)&NdB, g_NdB);

    for (int k = 0; k < K_STEPS; k++) {
        int last = (k == K_STEPS - 1) ? 1 : 0;
        const float* Ndin = (k & 1) ? NdB : NdA;
        float* Ndout = (k & 1) ? NdA : NdB;
        row_kernel<<<512, 256>>>(k, last, Ndin, Ndout, out);
    }
}